// round 8
// baseline (speedup 1.0000x reference)
#include <cuda_runtime.h>
#include <cuda_fp16.h>

#define BATCH    128
#define NPTS     16384
#define GL       48
#define GW       20
#define GH       18
#define SLAB     (GL * GW * GH)        // 17280 voxels
#define HALF_L   2.4f
#define HALF_W   1.0f

#define BLOCKS_PER_BATCH 4
#define THREADS          512
#define PTS_PER_BLOCK    (NPTS / BLOCKS_PER_BATCH)     // 4096
#define GROUPS           (PTS_PER_BLOCK / (THREADS*4)) // 2

#define SMEM_BYTES (SLAB * 2)          // char2 z-pair table = 34560 B

__global__ __launch_bounds__(THREADS, 4)
void pose_loss_kernel(const float* __restrict__ voxels,
                      const float* __restrict__ pts,
                      const float* __restrict__ hgt,
                      float* __restrict__ out)
{
    extern __shared__ char2 svox[];    // svox[i] = (q[i], q[i+1 or i if z==17])

    __shared__ float warp_red[THREADS / 32];
    __shared__ float s_scale;

    const int batch = blockIdx.x / BLOCKS_PER_BATCH;
    const int chunk = blockIdx.x % BLOCKS_PER_BATCH;
    const int tid   = threadIdx.x;
    const int lane  = tid & 31;
    const int wid   = tid >> 5;

    const float*  __restrict__ vsrc  = voxels + (size_t)batch * SLAB;
    const float4* __restrict__ vsrc4 = (const float4*)vsrc;

    // ---- pass 1: per-batch max|v| (block reduction) ----
    float m = 0.0f;
    for (int i = tid; i < SLAB / 4; i += THREADS) {
        const float4 a = vsrc4[i];
        m = fmaxf(m, fmaxf(fmaxf(fabsf(a.x), fabsf(a.y)),
                           fmaxf(fabsf(a.z), fabsf(a.w))));
    }
    #pragma unroll
    for (int off = 16; off > 0; off >>= 1)
        m = fmaxf(m, __shfl_xor_sync(0xFFFFFFFFu, m, off));
    if (lane == 0) warp_red[wid] = m;
    __syncthreads();
    if (tid == 0) {
        float mm = warp_red[0];
        #pragma unroll
        for (int w = 1; w < THREADS / 32; ++w) mm = fmaxf(mm, warp_red[w]);
        s_scale = fmaxf(mm, 1e-20f) * (1.0f / 127.0f);
        warp_red[0] = 127.0f / fmaxf(mm, 1e-20f);   // inverse scale broadcast
    }
    __syncthreads();
    const float inv_scale = warp_red[0];
    const float vscale    = s_scale;
    __syncthreads();   // warp_red reused below for the final sum

    // ---- pass 2: quantize + build z-pair table (L1/L2-hot reread) ----
    for (int i = tid; i < SLAB / 4; i += THREADS) {
        const int i4 = i * 4;
        const float4 a = vsrc4[i];
        int nidx = i4 + 4; if (nidx >= SLAB) nidx = SLAB - 1;
        const float nxt = vsrc[nidx];
        const int mz = (i4 + 1) % GH;     // z(i4)==17 <=> mz==0, etc.
        const float n0 = (mz == 0)  ? a.x : a.y;
        const float n1 = (mz == 17) ? a.y : a.z;
        const float n2 = (mz == 16) ? a.z : a.w;
        const float n3 = (mz == 15) ? a.w : nxt;

        const int qa0 = __float2int_rn(a.x * inv_scale);
        const int qn0 = __float2int_rn(n0  * inv_scale);
        const int qa1 = __float2int_rn(a.y * inv_scale);
        const int qn1 = __float2int_rn(n1  * inv_scale);
        const int qa2 = __float2int_rn(a.z * inv_scale);
        const int qn2 = __float2int_rn(n2  * inv_scale);
        const int qa3 = __float2int_rn(a.w * inv_scale);
        const int qn3 = __float2int_rn(n3  * inv_scale);

        uint2 pk;
        pk.x = (qa0 & 0xFF) | ((qn0 & 0xFF) << 8) |
               ((qa1 & 0xFF) << 16) | ((qn1 & 0xFF) << 24);
        pk.y = (qa2 & 0xFF) | ((qn2 & 0xFF) << 8) |
               ((qa3 & 0xFF) << 16) | ((qn3 & 0xFF) << 24);
        *(uint2*)&svox[i4] = pk;          // 8B aligned: byte offset = 8*i
    }
    __syncthreads();

    float acc = 0.0f;

    #pragma unroll
    for (int j = 0; j < GROUPS; ++j) {
        const size_t gp = (size_t)batch * NPTS + chunk * PTS_PER_BLOCK
                        + j * (THREADS * 4) + tid * 4;
        const float4* __restrict__ pf = (const float4*)(pts + gp * 3);
        const float4 a = pf[0], b = pf[1], c = pf[2];
        const float4 h = *(const float4*)(hgt + gp);

        const float PX[4] = { a.x, a.w, b.z, c.y };
        const float PY[4] = { a.y, b.x, b.w, c.z };
        const float PZ[4] = { a.z, b.y, c.x, c.w };
        const float HH[4] = { h.x, h.y, h.z, h.w };

        #pragma unroll
        for (int k = 0; k < 4; ++k) {
            const float x = PX[k] + HALF_L;
            const float y = PY[k] + HALF_W;
            const float z = PZ[k] + HH[k] * 0.5f;

            const int ix = __float2int_rd(x * 10.0f);
            const int iy = __float2int_rd(y * 10.0f);
            const int iz = __float2int_rd(z * 10.0f);

            // t = (l+1)/2 folded to (x - xm*0.1)*10
            const float tx = (x - (float)ix * 0.1f) * 10.0f;
            const float ty = (y - (float)iy * 0.1f) * 10.0f;
            const float tz = (z - (float)iz * 0.1f) * 10.0f;

            const int x0 = min(max(ix, 0), GL - 1);
            const int y0 = min(max(iy, 0), GW - 1);
            const int zp = min(max(iz, 0), GH - 1);
            const int x1 = min(x0 + 1, GL - 1);
            const int y1 = min(y0 + 1, GW - 1);

            // lower clamp: ref uses corner0==corner1 there; zeroing t matches exactly
            const float txp = (ix < 0) ? 0.0f : tx;
            const float typ = (iy < 0) ? 0.0f : ty;
            const float tzp = (iz < 0) ? 0.0f : tz;
            const float sxp = 1.0f - txp;
            const float syp = 1.0f - typ;
            const float szp = 1.0f - tzp;

            const int r0 = x0 * GW, r1 = x1 * GW;
            const char2 p00 = svox[(r0 + y0) * GH + zp];
            const char2 p01 = svox[(r0 + y1) * GH + zp];
            const char2 p10 = svox[(r1 + y0) * GH + zp];
            const char2 p11 = svox[(r1 + y1) * GH + zp];

            const float v00 = fmaf((float)p00.y, tzp, (float)p00.x * szp);
            const float v01 = fmaf((float)p01.y, tzp, (float)p01.x * szp);
            const float v10 = fmaf((float)p10.y, tzp, (float)p10.x * szp);
            const float v11 = fmaf((float)p11.y, tzp, (float)p11.x * szp);

            const float vx1 = fmaf(v11, typ, v10 * syp);
            const float vx0 = fmaf(v01, typ, v00 * syp);
            const float sdf = fmaf(vx1, txp, vx0 * sxp) * vscale;

            const float ax = fabsf(sdf);
            acc += (ax < 1.0f) ? (0.5f * sdf * sdf) : (ax - 0.5f);
        }
    }

    // ---- block reduction ----
    #pragma unroll
    for (int off = 16; off > 0; off >>= 1)
        acc += __shfl_xor_sync(0xFFFFFFFFu, acc, off);

    if (lane == 0) warp_red[wid] = acc;
    __syncthreads();

    if (wid == 0) {
        float s = (lane < THREADS / 32) ? warp_red[lane] : 0.0f;
        #pragma unroll
        for (int off = 8; off > 0; off >>= 1)
            s += __shfl_xor_sync(0xFFFFFFFFu, s, off);
        if (lane == 0)
            atomicAdd(out, s * (1.0f / ((float)BATCH * (float)NPTS)));
    }
}

extern "C" void kernel_launch(void* const* d_in, const int* in_sizes, int n_in,
                              void* d_out, int out_size)
{
    const float* voxels = (const float*)d_in[0];
    const float* pts    = (const float*)d_in[1];
    const float* hgt    = (const float*)d_in[2];
    float* out          = (float*)d_out;

    cudaMemsetAsync(out, 0, sizeof(float));

    const int grid = BATCH * BLOCKS_PER_BATCH;   // 512 CTAs, one wave @ 4/SM
    pose_loss_kernel<<<grid, THREADS, SMEM_BYTES>>>(voxels, pts, hgt, out);
}